// round 12
// baseline (speedup 1.0000x reference)
#include <cuda_runtime.h>
#include <cuda_fp16.h>
#include <stdint.h>

#define N_NODES 100000
#define GAMMA 0.5f
#define FIX_SCALE 65536.0f          // 2^16 fixed-point for per-node mask sum
#define INV_FIX_SCALE (1.0f / 65536.0f)
#define OUT_GRID 152                // one persistent block per SM
#define OUT_BLOCK 1024
#define SMEM_BYTES (N_NODES * 2)    // full avg table as fp16: 195.3KB < 227KB limit

// packed per-node accumulator (32-bit): bits[24:32)=count, bits[0:24)=sum*2^16
// Max node degree ~110 (Poisson(64) over 100K nodes) < 255; max packed sum
// 110*2^16 = 7.2M < 2^24, so the sum field never carries into the count field.
// Zero-initialized at load; avg_kernel re-zeroes after each read, so every
// kernel_launch invocation (and graph replay) sees a clean table.
__device__ unsigned g_pack[N_NODES];
__device__ __half g_avg_h[N_NODES];

__device__ __forceinline__ unsigned pack_edge(float m) {
    unsigned fix = __float2uint_rn(m * FIX_SCALE);
    return (1u << 24) | fix;
}

// Scatter: one 32-bit REDG per edge carrying both count(+1) and fixed-point sum.
// Testing: REDG.32 should issue ~1.55x faster than REDG.64 (STG.32=5 vs STG.64=7.75).
__global__ void scatter_kernel(const float* __restrict__ mask,
                               const int* __restrict__ src,
                               int E) {
    int i4 = (blockIdx.x * blockDim.x + threadIdx.x) * 4;
    if (i4 + 3 < E) {
        float4 m = __ldcg(reinterpret_cast<const float4*>(mask + i4));
        int4 s = __ldcg(reinterpret_cast<const int4*>(src + i4));
        atomicAdd(&g_pack[s.x], pack_edge(m.x));
        atomicAdd(&g_pack[s.y], pack_edge(m.y));
        atomicAdd(&g_pack[s.z], pack_edge(m.z));
        atomicAdd(&g_pack[s.w], pack_edge(m.w));
    } else {
        for (int i = i4; i < E; i++) {
            atomicAdd(&g_pack[src[i]], pack_edge(mask[i]));
        }
    }
}

// avg + reset: reads the packed accumulator, produces fp16 avg, and zeroes the
// accumulator for the next invocation.
__global__ void avg_kernel() {
    int i = blockIdx.x * blockDim.x + threadIdx.x;
    if (i < N_NODES) {
        unsigned p = g_pack[i];
        g_pack[i] = 0u;
        float cnt = (float)(p >> 24);
        float sum = (float)(p & 0x00ffffffu) * INV_FIX_SCALE;
        g_avg_h[i] = __float2half_rn(sum / fmaxf(cnt, 1.0f));
    }
}

// out[e] = 0.5*mask[e] + 0.25*(avg[src[e]] + avg[dst[e]])
// Full fp16 avg table in smem: every lookup is one LDS. Simple x4 grid-stride
// (empirically the best schedule across R6-R11). UNCHANGED from R10 best.
__global__ void __launch_bounds__(OUT_BLOCK, 1)
out_kernel(const float* __restrict__ mask,
           const int* __restrict__ src,
           const int* __restrict__ dst,
           float* __restrict__ out,
           int E) {
    extern __shared__ __half s_avg[];

    // Stage table: 195.3KB via 128-bit chunks.
    {
        const uint4* gsrc = reinterpret_cast<const uint4*>(g_avg_h);
        uint4* sdst = reinterpret_cast<uint4*>(s_avg);
        const int nchunk = (N_NODES * 2) / 16;  // 12500
        for (int i = threadIdx.x; i < nchunk; i += OUT_BLOCK)
            sdst[i] = gsrc[i];
    }
    __syncthreads();

    int nG = E >> 2;
    int stride = gridDim.x * OUT_BLOCK;
    for (int g = blockIdx.x * OUT_BLOCK + threadIdx.x; g < nG; g += stride) {
        int i4 = g * 4;
        float4 m = __ldcg(reinterpret_cast<const float4*>(mask + i4));
        int4 s = __ldcg(reinterpret_cast<const int4*>(src + i4));
        int4 d = __ldcg(reinterpret_cast<const int4*>(dst + i4));

        float vs0 = __half2float(s_avg[s.x]);
        float vs1 = __half2float(s_avg[s.y]);
        float vs2 = __half2float(s_avg[s.z]);
        float vs3 = __half2float(s_avg[s.w]);
        float vd0 = __half2float(s_avg[d.x]);
        float vd1 = __half2float(s_avg[d.y]);
        float vd2 = __half2float(s_avg[d.z]);
        float vd3 = __half2float(s_avg[d.w]);

        float4 o;
        o.x = (1.0f - GAMMA) * m.x + (GAMMA * 0.5f) * (vs0 + vd0);
        o.y = (1.0f - GAMMA) * m.y + (GAMMA * 0.5f) * (vs1 + vd1);
        o.z = (1.0f - GAMMA) * m.z + (GAMMA * 0.5f) * (vs2 + vd2);
        o.w = (1.0f - GAMMA) * m.w + (GAMMA * 0.5f) * (vs3 + vd3);
        __stcg(reinterpret_cast<float4*>(out + i4), o);
    }

    // tail (E % 4 leftovers)
    int tail = E & 3;
    if (blockIdx.x == 0 && (int)threadIdx.x < tail) {
        int i = (E & ~3) + threadIdx.x;
        float a = __half2float(s_avg[src[i]]) + __half2float(s_avg[dst[i]]);
        out[i] = (1.0f - GAMMA) * mask[i] + (GAMMA * 0.5f) * a;
    }
}

extern "C" void kernel_launch(void* const* d_in, const int* in_sizes, int n_in,
                              void* d_out, int out_size) {
    const float* mask = (const float*)d_in[0];
    const int* edge_index = (const int*)d_in[1];  // int32 (JAX x64 disabled)
    float* out = (float*)d_out;

    int E = in_sizes[0];
    const int* src = edge_index;       // row 0
    const int* dst = edge_index + E;   // row 1

    cudaFuncSetAttribute(out_kernel, cudaFuncAttributeMaxDynamicSharedMemorySize,
                         SMEM_BYTES);

    {
        int threads = 256;
        int work = (E + 3) / 4;
        int blocks = (work + threads - 1) / threads;
        scatter_kernel<<<blocks, threads>>>(mask, src, E);
    }
    {
        int threads = 512;
        int blocks = (N_NODES + threads - 1) / threads;
        avg_kernel<<<blocks, threads>>>();
    }
    {
        out_kernel<<<OUT_GRID, OUT_BLOCK, SMEM_BYTES>>>(mask, src, dst, out, E);
    }
}

// round 13
// speedup vs baseline: 1.2577x; 1.2577x over previous
#include <cuda_runtime.h>
#include <cuda_fp16.h>
#include <stdint.h>

#define N_NODES 100000
#define GAMMA 0.5f
#define FIX_SCALE 8388608.0f        // 2^23
#define INV_FIX_SCALE (1.0f / 8388608.0f)
#define OUT_GRID 152                // one persistent block per SM
#define OUT_BLOCK 1024
#define SMEM_BYTES (N_NODES * 2)    // full avg table as fp16: 195.3KB < 227KB limit

// packed per-node accumulator: high 32 = count, low 32 = fixed-point sum (2^23 scale)
__device__ unsigned long long g_pack[N_NODES];
__device__ __half g_avg_h[N_NODES];

__global__ void zero_kernel() {
    int i = blockIdx.x * blockDim.x + threadIdx.x;
    if (i < N_NODES) g_pack[i] = 0ull;
}

__device__ __forceinline__ unsigned long long pack_edge(float m) {
    unsigned fix = __float2uint_rn(m * FIX_SCALE);
    return (1ull << 32) | (unsigned long long)fix;
}

// Scatter: one 64-bit REDG per edge carrying both count(+1) and fixed-point sum.
// At the per-SM spread-REDG lane-issue floor (~29-30us): 6.4M lanes / 152 SMs
// x 1.29 cyc/lane. Verified width-independent (R7/R11/R12).
__global__ void scatter_kernel(const float* __restrict__ mask,
                               const int* __restrict__ src,
                               int E) {
    int i4 = (blockIdx.x * blockDim.x + threadIdx.x) * 4;
    if (i4 + 3 < E) {
        float4 m = __ldcg(reinterpret_cast<const float4*>(mask + i4));
        int4 s = __ldcg(reinterpret_cast<const int4*>(src + i4));
        atomicAdd(&g_pack[s.x], pack_edge(m.x));
        atomicAdd(&g_pack[s.y], pack_edge(m.y));
        atomicAdd(&g_pack[s.z], pack_edge(m.z));
        atomicAdd(&g_pack[s.w], pack_edge(m.w));
    } else {
        for (int i = i4; i < E; i++) {
            atomicAdd(&g_pack[src[i]], pack_edge(mask[i]));
        }
    }
}

__global__ void avg_kernel() {
    int i = blockIdx.x * blockDim.x + threadIdx.x;
    if (i < N_NODES) {
        unsigned long long p = g_pack[i];
        float cnt = (float)(unsigned)(p >> 32);
        float sum = (float)(unsigned)(p & 0xffffffffull) * INV_FIX_SCALE;
        g_avg_h[i] = __float2half_rn(sum / fmaxf(cnt, 1.0f));
    }
}

// out[e] = 0.5*mask[e] + 0.25*(avg[src[e]] + avg[dst[e]])
// Full fp16 avg table in smem: every lookup is one LDS. Simple x4 grid-stride
// (empirically the best schedule across R6-R12).
__global__ void __launch_bounds__(OUT_BLOCK, 1)
out_kernel(const float* __restrict__ mask,
           const int* __restrict__ src,
           const int* __restrict__ dst,
           float* __restrict__ out,
           int E) {
    extern __shared__ __half s_avg[];

    // Stage table: 195.3KB via 128-bit chunks.
    {
        const uint4* gsrc = reinterpret_cast<const uint4*>(g_avg_h);
        uint4* sdst = reinterpret_cast<uint4*>(s_avg);
        const int nchunk = (N_NODES * 2) / 16;  // 12500
        for (int i = threadIdx.x; i < nchunk; i += OUT_BLOCK)
            sdst[i] = gsrc[i];
    }
    __syncthreads();

    int nG = E >> 2;
    int stride = gridDim.x * OUT_BLOCK;
    for (int g = blockIdx.x * OUT_BLOCK + threadIdx.x; g < nG; g += stride) {
        int i4 = g * 4;
        float4 m = __ldcg(reinterpret_cast<const float4*>(mask + i4));
        int4 s = __ldcg(reinterpret_cast<const int4*>(src + i4));
        int4 d = __ldcg(reinterpret_cast<const int4*>(dst + i4));

        float vs0 = __half2float(s_avg[s.x]);
        float vs1 = __half2float(s_avg[s.y]);
        float vs2 = __half2float(s_avg[s.z]);
        float vs3 = __half2float(s_avg[s.w]);
        float vd0 = __half2float(s_avg[d.x]);
        float vd1 = __half2float(s_avg[d.y]);
        float vd2 = __half2float(s_avg[d.z]);
        float vd3 = __half2float(s_avg[d.w]);

        float4 o;
        o.x = (1.0f - GAMMA) * m.x + (GAMMA * 0.5f) * (vs0 + vd0);
        o.y = (1.0f - GAMMA) * m.y + (GAMMA * 0.5f) * (vs1 + vd1);
        o.z = (1.0f - GAMMA) * m.z + (GAMMA * 0.5f) * (vs2 + vd2);
        o.w = (1.0f - GAMMA) * m.w + (GAMMA * 0.5f) * (vs3 + vd3);
        __stcg(reinterpret_cast<float4*>(out + i4), o);
    }

    // tail (E % 4 leftovers)
    int tail = E & 3;
    if (blockIdx.x == 0 && (int)threadIdx.x < tail) {
        int i = (E & ~3) + threadIdx.x;
        float a = __half2float(s_avg[src[i]]) + __half2float(s_avg[dst[i]]);
        out[i] = (1.0f - GAMMA) * mask[i] + (GAMMA * 0.5f) * a;
    }
}

extern "C" void kernel_launch(void* const* d_in, const int* in_sizes, int n_in,
                              void* d_out, int out_size) {
    const float* mask = (const float*)d_in[0];
    const int* edge_index = (const int*)d_in[1];  // int32 (JAX x64 disabled)
    float* out = (float*)d_out;

    int E = in_sizes[0];
    const int* src = edge_index;       // row 0
    const int* dst = edge_index + E;   // row 1

    cudaFuncSetAttribute(out_kernel, cudaFuncAttributeMaxDynamicSharedMemorySize,
                         SMEM_BYTES);

    {
        int threads = 512;
        int blocks = (N_NODES + threads - 1) / threads;
        zero_kernel<<<blocks, threads>>>();
    }
    {
        int threads = 256;
        int work = (E + 3) / 4;
        int blocks = (work + threads - 1) / threads;
        scatter_kernel<<<blocks, threads>>>(mask, src, E);
    }
    {
        int threads = 512;
        int blocks = (N_NODES + threads - 1) / threads;
        avg_kernel<<<blocks, threads>>>();
    }
    {
        out_kernel<<<OUT_GRID, OUT_BLOCK, SMEM_BYTES>>>(mask, src, dst, out, E);
    }
}